// round 7
// baseline (speedup 1.0000x reference)
#include <cuda_runtime.h>
#include <cuda_bf16.h>
#include <cstdint>

#define BB 2
#define SS 2048
#define EE 1024
#define HH 16
#define DD 64

__device__ float g_qkv[3 * BB * HH * SS * DD];   // [which][b][h][s][d]
__device__ float g_ctx[BB * SS * EE];            // [b][s][h*64+d]

// bf16 hi/lo split buffers
__device__ __nv_bfloat16 g_a_hi[4096 * 1024];
__device__ __nv_bfloat16 g_a_lo[4096 * 1024];
__device__ __nv_bfloat16 g_wq_hi[3072 * 1024];
__device__ __nv_bfloat16 g_wq_lo[3072 * 1024];
__device__ __nv_bfloat16 g_wo_hi[1024 * 1024];
__device__ __nv_bfloat16 g_wo_lo[1024 * 1024];

// ===========================================================================
// helpers
// ===========================================================================
__device__ __forceinline__ uint32_t smem_u32(const void* p) {
    uint32_t a;
    asm("{ .reg .u64 t; cvta.to.shared.u64 t, %1; cvt.u32.u64 %0, t; }"
        : "=r"(a) : "l"(p));
    return a;
}
__device__ __forceinline__ void cp_async16(uint32_t saddr, const void* g) {
    asm volatile("cp.async.cg.shared.global [%0], [%1], 16;\n" :: "r"(saddr), "l"(g));
}
__device__ __forceinline__ void cp_commit() {
    asm volatile("cp.async.commit_group;\n" ::: "memory");
}
__device__ __forceinline__ void ldsm4(uint32_t& r0, uint32_t& r1, uint32_t& r2,
                                      uint32_t& r3, uint32_t a) {
    asm volatile("ldmatrix.sync.aligned.m8n8.x4.shared.b16 {%0,%1,%2,%3}, [%4];"
                 : "=r"(r0), "=r"(r1), "=r"(r2), "=r"(r3) : "r"(a));
}
__device__ __forceinline__ void mma_bf16(float* c, const uint32_t* a, uint32_t b0,
                                         uint32_t b1) {
    asm volatile(
        "mma.sync.aligned.m16n8k16.row.col.f32.bf16.bf16.f32 "
        "{%0,%1,%2,%3},{%4,%5,%6,%7},{%8,%9},{%0,%1,%2,%3};"
        : "+f"(c[0]), "+f"(c[1]), "+f"(c[2]), "+f"(c[3])
        : "r"(a[0]), "r"(a[1]), "r"(a[2]), "r"(a[3]), "r"(b0), "r"(b1));
}
__device__ __forceinline__ void split4(float4 v, uint32_t& h01, uint32_t& h23,
                                       uint32_t& l01, uint32_t& l23) {
    asm("cvt.rn.bf16x2.f32 %0, %1, %2;" : "=r"(h01) : "f"(v.y), "f"(v.x));
    asm("cvt.rn.bf16x2.f32 %0, %1, %2;" : "=r"(h23) : "f"(v.w), "f"(v.z));
    float q0 = v.x - __uint_as_float(h01 << 16);
    float q1 = v.y - __uint_as_float(h01 & 0xffff0000u);
    float q2 = v.z - __uint_as_float(h23 << 16);
    float q3 = v.w - __uint_as_float(h23 & 0xffff0000u);
    asm("cvt.rn.bf16x2.f32 %0, %1, %2;" : "=r"(l01) : "f"(q1), "f"(q0));
    asm("cvt.rn.bf16x2.f32 %0, %1, %2;" : "=r"(l23) : "f"(q3), "f"(q2));
}
// packed f32x2
__device__ __forceinline__ uint64_t f2pack(float a, float b) {
    uint64_t r;
    asm("mov.b64 %0, {%1, %2};" : "=l"(r) : "f"(a), "f"(b));
    return r;
}
__device__ __forceinline__ uint64_t fma2(uint64_t a, uint64_t b, uint64_t c) {
    uint64_t d;
    asm("fma.rn.f32x2 %0, %1, %2, %3;" : "=l"(d) : "l"(a), "l"(b), "l"(c));
    return d;
}
__device__ __forceinline__ void f2unpack(uint64_t v, float& a, float& b) {
    asm("mov.b64 {%0, %1}, %2;" : "=f"(a), "=f"(b) : "l"(v));
}

// ===========================================================================
// fp32 -> bf16 hi/lo split
// ===========================================================================
template <int DST>
__global__ __launch_bounds__(256) void cvt_split(const float4* __restrict__ src) {
    int i = blockIdx.x * 256 + threadIdx.x;
    float4 v = src[i];
    uint32_t h01, h23, l01, l23;
    split4(v, h01, h23, l01, l23);
    uint2* hp = (uint2*)(DST == 0 ? g_a_hi : DST == 1 ? g_wq_hi : g_wo_hi);
    uint2* lp = (uint2*)(DST == 0 ? g_a_lo : DST == 1 ? g_wq_lo : g_wo_lo);
    hp[i] = make_uint2(h01, h23);
    lp[i] = make_uint2(l01, l23);
}

// ===========================================================================
// HMMA bf16-split GEMM (unchanged from R6, passing)
// ===========================================================================
#define TILE_B 10240
#define BUF_B (4 * TILE_B)
#define GEMM_SMEM (2 * BUF_B)

template <int MODE, int N, int K>
__global__ __launch_bounds__(256, 2) void tgemm(const float* __restrict__ bias,
                                                float* __restrict__ Cout) {
    extern __shared__ char dsm[];
    uint32_t sbase = smem_u32(dsm);

    const __nv_bfloat16* Ah = g_a_hi;
    const __nv_bfloat16* Al = g_a_lo;
    const __nv_bfloat16* Wh = (MODE == 1) ? g_wq_hi : g_wo_hi;
    const __nv_bfloat16* Wl = (MODE == 1) ? g_wq_lo : g_wo_lo;

    int tid = threadIdx.x, lane = tid & 31, wid = tid >> 5;
    int wm = wid & 3, wn = wid >> 2;
    int m0 = blockIdx.y * 128, n0 = blockIdx.x * 128;

    float acc[2][8][4];
#pragma unroll
    for (int i = 0; i < 2; i++)
#pragma unroll
        for (int j = 0; j < 8; j++)
#pragma unroll
            for (int q = 0; q < 4; q++) acc[i][j][q] = 0.f;

    const int NC = K / 32;
    const int lrow = tid >> 2;
    const int seg = tid & 3;

    auto issue = [&](int c) {
        int buf = c & 1;
        uint32_t sb = sbase + buf * BUF_B;
        size_t gcol = (size_t)c * 32 + seg * 8;
#pragma unroll
        for (int rr = 0; rr < 2; rr++) {
            int row = lrow + rr * 64;
            uint32_t soff = (uint32_t)(row * 80 + seg * 16);
            cp_async16(sb + 0 * TILE_B + soff, Ah + (size_t)(m0 + row) * K + gcol);
            cp_async16(sb + 1 * TILE_B + soff, Al + (size_t)(m0 + row) * K + gcol);
            cp_async16(sb + 2 * TILE_B + soff, Wh + (size_t)(n0 + row) * K + gcol);
            cp_async16(sb + 3 * TILE_B + soff, Wl + (size_t)(n0 + row) * K + gcol);
        }
        cp_commit();
    };

    issue(0);

    for (int c = 0; c < NC; c++) {
        if (c + 1 < NC) {
            issue(c + 1);
            asm volatile("cp.async.wait_group 1;\n" ::: "memory");
        } else {
            asm volatile("cp.async.wait_group 0;\n" ::: "memory");
        }
        __syncthreads();

        uint32_t sb = sbase + (c & 1) * BUF_B;
        uint32_t a_addr = sb + (uint32_t)((wm * 32 + (lane & 15)) * 80 + (lane >> 4) * 16);
        uint32_t b_addr = sb + 2 * TILE_B +
                          (uint32_t)((wn * 64 + (lane >> 4) * 8 + (lane & 7)) * 80 +
                                     ((lane >> 3) & 1) * 16);

#pragma unroll
        for (int ks = 0; ks < 2; ks++) {
            uint32_t ah[2][4], al[2][4];
#pragma unroll
            for (int mb = 0; mb < 2; mb++) {
                uint32_t ao = a_addr + ks * 32 + mb * (16 * 80);
                ldsm4(ah[mb][0], ah[mb][1], ah[mb][2], ah[mb][3], ao);
                ldsm4(al[mb][0], al[mb][1], al[mb][2], al[mb][3], ao + TILE_B);
            }
#pragma unroll
            for (int np = 0; np < 4; np++) {
                uint32_t bo = b_addr + ks * 32 + np * (16 * 80);
                uint32_t h0, h1, h2, h3, l0, l1, l2, l3;
                ldsm4(h0, h1, h2, h3, bo);
                ldsm4(l0, l1, l2, l3, bo + TILE_B);
#pragma unroll
                for (int mb = 0; mb < 2; mb++) {
                    mma_bf16(acc[mb][2 * np],     ah[mb], h0, h1);
                    mma_bf16(acc[mb][2 * np],     al[mb], h0, h1);
                    mma_bf16(acc[mb][2 * np],     ah[mb], l0, l1);
                    mma_bf16(acc[mb][2 * np + 1], ah[mb], h2, h3);
                    mma_bf16(acc[mb][2 * np + 1], al[mb], h2, h3);
                    mma_bf16(acc[mb][2 * np + 1], ah[mb], l2, l3);
                }
            }
        }
        __syncthreads();
    }

    int lr = lane >> 2, lc = lane & 3;
#pragma unroll
    for (int mb = 0; mb < 2; mb++) {
#pragma unroll
        for (int nb = 0; nb < 8; nb++) {
            int n = n0 + wn * 64 + nb * 8 + lc * 2;
            float2 bv = *(const float2*)(bias + n);
            int m_lo = m0 + wm * 32 + mb * 16 + lr;
            float* a4 = acc[mb][nb];
            if (MODE == 0) {
                *(float2*)(Cout + (size_t)m_lo * N + n) =
                    make_float2(a4[0] + bv.x, a4[1] + bv.y);
                *(float2*)(Cout + (size_t)(m_lo + 8) * N + n) =
                    make_float2(a4[2] + bv.x, a4[3] + bv.y);
            } else {
                int which = n >> 10;
                int h = (n & 1023) >> 6;
                int d = n & 63;
#pragma unroll
                for (int half = 0; half < 2; half++) {
                    int m = m_lo + half * 8;
                    int b = m >> 11;
                    int s = m & 2047;
                    float* dst = g_qkv +
                        ((((size_t)which * BB + b) * HH + h) * SS + s) * DD + d;
                    *(float2*)dst = make_float2(a4[2 * half] + bv.x,
                                                a4[2 * half + 1] + bv.y);
                }
            }
        }
    }
}

// ===========================================================================
// Attention v3: softmax over HEAD axis; TQ=16, 512 threads, f32x2 ctx FMA.
// thread: h = tid&15, dl = (tid>>4)&15 (d-slice of 4 floats), qs = tid>>8.
// Per KC=4 chunk: A: partial scores over 4-float slice -> sp[dl][q][h];
// reduce (tid<256, thread=(qr,h)): sum 16 partials, exp, width-16 shfl-sum,
// p -> pb; C: ctx f32x2 FMA (V slice read once per (kj,h,dl), 2x qs reuse).
// ===========================================================================
#define TQ 16
#define KC 4
#define RP 17
#define BUFQ (KC * 16 * RP)             // 1088 f4 per tensor per buffer
#define SP_OFF (4 * BUFQ)               // sp: [dl16][q16][h16] f4 = 4096 f4
#define P_OFF (SP_OFF + 4096)           // pb: [q16][h16] f4 = 256 f4
#define ATTN_SMEM ((P_OFF + 256) * 16)  // 139264 bytes

__global__ __launch_bounds__(512, 1) void attn_kernel() {
    extern __shared__ float4 smem[];

    int tid = threadIdx.x;
    int h = tid & 15;
    int dl = (tid >> 4) & 15;
    int qs = tid >> 8;                 // 0..1
    int blk = blockIdx.x;
    int b = blk >> 7;                  // 128 q-tiles per batch
    int q0 = (blk & 127) * TQ;

    const float4* Kg = (const float4*)g_qkv + ((1 * BB + b) * HH) * SS * 16;
    const float4* Vg = (const float4*)g_qkv + ((2 * BB + b) * HH) * SS * 16;

    uint32_t sbase = smem_u32(smem);
    float4* sp = smem + SP_OFF;
    float4* pb = smem + P_OFF;

    // q slices (4 floats at d = dl*4) for 8 queries
    float4 qv[8];
#pragma unroll
    for (int qi = 0; qi < 8; qi++) {
        qv[qi] = ((const float4*)g_qkv)[(((0 * BB + b) * HH + h) * SS +
                                         (q0 + qs * 8 + qi)) * 16 + dl];
    }

    // ctx accumulators as f32x2 pairs
    uint64_t av[8][2];
#pragma unroll
    for (int qi = 0; qi < 8; qi++) {
        av[qi][0] = f2pack(0.f, 0.f);
        av[qi][1] = f2pack(0.f, 0.f);
    }

    const float inv_scale = 1.0f / 32.0f;
    const int NC = SS / KC;

    // cp.async: 1024 f4 per tensor per chunk, 2 per thread
    auto issue = [&](int kb0, int bi) {
#pragma unroll
        for (int rr = 0; rr < 2; rr++) {
            int f = tid + rr * 512;
            int i = f & 15;
            int row = f >> 4;          // kj*16 + hh
            int kj = row >> 4;
            int hh = row & 15;
            int gi = (hh * SS + kb0 + kj) * 16 + i;
            uint32_t so = (uint32_t)((bi * BUFQ + row * RP + i) * 16);
            cp_async16(sbase + so, (const void*)(Kg + gi));
            cp_async16(sbase + so + (uint32_t)(2 * BUFQ * 16), (const void*)(Vg + gi));
        }
        cp_commit();
    };

    issue(0, 0);

    for (int c = 0; c < NC; c++) {
        if (c + 1 < NC) {
            issue((c + 1) * KC, (c + 1) & 1);
            asm volatile("cp.async.wait_group 1;\n" ::: "memory");
        } else {
            asm volatile("cp.async.wait_group 0;\n" ::: "memory");
        }
        __syncthreads();

        const float4* kbuf = smem + (c & 1) * BUFQ;
        const float4* vbuf = kbuf + 2 * BUFQ;

        // ---- Phase A: partial scores over this thread's 4-float d-slice ----
        float s[8][KC];
#pragma unroll
        for (int kj = 0; kj < KC; kj++) {
            float4 k4 = kbuf[(kj * 16 + h) * RP + dl];
#pragma unroll
            for (int qi = 0; qi < 8; qi++) {
                s[qi][kj] = qv[qi].x * k4.x + qv[qi].y * k4.y +
                            qv[qi].z * k4.z + qv[qi].w * k4.w;
            }
        }
#pragma unroll
        for (int qi = 0; qi < 8; qi++)
            sp[dl * 256 + (qs * 8 + qi) * 16 + h] =
                make_float4(s[qi][0], s[qi][1], s[qi][2], s[qi][3]);
        __syncthreads();

        // ---- Reduce + softmax over heads (256 threads: (qr, h)) ----
        if (tid < 256) {
            int qr = tid >> 4;
            float4 t = sp[qr * 16 + h];
#pragma unroll
            for (int d2 = 1; d2 < 16; d2++) {
                float4 u = sp[d2 * 256 + qr * 16 + h];
                t.x += u.x; t.y += u.y; t.z += u.z; t.w += u.w;
            }
            float4 e;
            e.x = __expf(t.x * inv_scale);
            e.y = __expf(t.y * inv_scale);
            e.z = __expf(t.z * inv_scale);
            e.w = __expf(t.w * inv_scale);
            float4 sum = e;
#pragma unroll
            for (int o = 8; o; o >>= 1) {
                sum.x += __shfl_xor_sync(0xffffffffu, sum.x, o, 16);
                sum.y += __shfl_xor_sync(0xffffffffu, sum.y, o, 16);
                sum.z += __shfl_xor_sync(0xffffffffu, sum.z, o, 16);
                sum.w += __shfl_xor_sync(0xffffffffu, sum.w, o, 16);
            }
            float4 p4;
            p4.x = __fdividef(e.x, sum.x);
            p4.y = __fdividef(e.y, sum.y);
            p4.z = __fdividef(e.z, sum.z);
            p4.w = __fdividef(e.w, sum.w);
            pb[qr * 16 + h] = p4;
        }
        __syncthreads();

        // ---- Phase C: ctx accumulation (f32x2) ----
        float4 pq[8];
#pragma unroll
        for (int qi = 0; qi < 8; qi++) pq[qi] = pb[(qs * 8 + qi) * 16 + h];

#pragma unroll
        for (int kj = 0; kj < KC; kj++) {
            float4 v4 = vbuf[(kj * 16 + h) * RP + dl];
            uint64_t vlo = f2pack(v4.x, v4.y);
            uint64_t vhi = f2pack(v4.z, v4.w);
#pragma unroll
            for (int qi = 0; qi < 8; qi++) {
                float pk = (kj == 0) ? pq[qi].x : (kj == 1) ? pq[qi].y
                         : (kj == 2) ? pq[qi].z : pq[qi].w;
                uint64_t pk2 = f2pack(pk, pk);
                av[qi][0] = fma2(pk2, vlo, av[qi][0]);
                av[qi][1] = fma2(pk2, vhi, av[qi][1]);
            }
        }
        __syncthreads();
    }

    // output: ctx[b][q0+qs*8+qi][h*64 + dl*4]
#pragma unroll
    for (int qi = 0; qi < 8; qi++) {
        float4 o;
        f2unpack(av[qi][0], o.x, o.y);
        f2unpack(av[qi][1], o.z, o.w);
        ((float4*)g_ctx)[((size_t)(b * SS + q0 + qs * 8 + qi) * EE + h * DD + dl * 4) >> 2] = o;
    }
}

// ===========================================================================
extern "C" void kernel_launch(void* const* d_in, const int* in_sizes, int n_in,
                              void* d_out, int out_size) {
    const float* x     = (const float*)d_in[0];
    const float* w_qkv = (const float*)d_in[1];
    const float* b_qkv = (const float*)d_in[2];
    const float* w_out = (const float*)d_in[3];
    const float* b_out = (const float*)d_in[4];
    float* out = (float*)d_out;

    cudaFuncSetAttribute(tgemm<1, 3072, 1024>, cudaFuncAttributeMaxDynamicSharedMemorySize, GEMM_SMEM);
    cudaFuncSetAttribute(tgemm<0, 1024, 1024>, cudaFuncAttributeMaxDynamicSharedMemorySize, GEMM_SMEM);
    cudaFuncSetAttribute(attn_kernel, cudaFuncAttributeMaxDynamicSharedMemorySize, ATTN_SMEM);

    cvt_split<0><<<(4096 * 1024 / 4) / 256, 256>>>((const float4*)x);
    cvt_split<1><<<(3072 * 1024 / 4) / 256, 256>>>((const float4*)w_qkv);
    cvt_split<2><<<(1024 * 1024 / 4) / 256, 256>>>((const float4*)w_out);

    {
        dim3 grid(3072 / 128, 4096 / 128);
        tgemm<1, 3072, 1024><<<grid, 256, GEMM_SMEM>>>(b_qkv, nullptr);
    }
    attn_kernel<<<BB * (SS / TQ), 512, ATTN_SMEM>>>();
    {
        float* ctxp = nullptr;
        cudaGetSymbolAddress((void**)&ctxp, g_ctx);
        cvt_split<0><<<(4096 * 1024 / 4) / 256, 256>>>((const float4*)ctxp);
        dim3 grid(1024 / 128, 4096 / 128);
        tgemm<0, 1024, 1024><<<grid, 256, GEMM_SMEM>>>(b_out, out);
    }
}

// round 8
// speedup vs baseline: 2.5863x; 2.5863x over previous
#include <cuda_runtime.h>
#include <cuda_bf16.h>
#include <cstdint>

#define BB 2
#define SS 2048
#define EE 1024
#define HH 16
#define DD 64
#define QKPLANE (BB * HH * SS * DD)          // 4194304
#define SPLANE ((size_t)SS * SS)             // 4194304 per (b,h)

__device__ float g_qkv[3 * QKPLANE];         // [which][b][h][s][d]
__device__ float g_ctx[BB * SS * EE];        // [b][s][h*64+d]
__device__ float g_S[(size_t)BB * HH * SS * SS];          // 512MB scores
__device__ __nv_bfloat16 g_p_hi[(size_t)BB * HH * SS * SS];
__device__ __nv_bfloat16 g_p_lo[(size_t)BB * HH * SS * SS];

__device__ __nv_bfloat16 g_a_hi[4096 * 1024];
__device__ __nv_bfloat16 g_a_lo[4096 * 1024];
__device__ __nv_bfloat16 g_wq_hi[3072 * 1024];
__device__ __nv_bfloat16 g_wq_lo[3072 * 1024];
__device__ __nv_bfloat16 g_wo_hi[1024 * 1024];
__device__ __nv_bfloat16 g_wo_lo[1024 * 1024];
__device__ __nv_bfloat16 g_q_hi[QKPLANE], g_q_lo[QKPLANE];
__device__ __nv_bfloat16 g_k_hi[QKPLANE], g_k_lo[QKPLANE];
__device__ __nv_bfloat16 g_vt_hi[QKPLANE], g_vt_lo[QKPLANE];   // [b][h][d][k]

// ===========================================================================
// helpers
// ===========================================================================
__device__ __forceinline__ uint32_t smem_u32(const void* p) {
    uint32_t a;
    asm("{ .reg .u64 t; cvta.to.shared.u64 t, %1; cvt.u32.u64 %0, t; }"
        : "=r"(a) : "l"(p));
    return a;
}
__device__ __forceinline__ void cp_async16(uint32_t saddr, const void* g) {
    asm volatile("cp.async.cg.shared.global [%0], [%1], 16;\n" :: "r"(saddr), "l"(g));
}
__device__ __forceinline__ void cp_commit() {
    asm volatile("cp.async.commit_group;\n" ::: "memory");
}
__device__ __forceinline__ void ldsm4(uint32_t& r0, uint32_t& r1, uint32_t& r2,
                                      uint32_t& r3, uint32_t a) {
    asm volatile("ldmatrix.sync.aligned.m8n8.x4.shared.b16 {%0,%1,%2,%3}, [%4];"
                 : "=r"(r0), "=r"(r1), "=r"(r2), "=r"(r3) : "r"(a));
}
__device__ __forceinline__ void mma_bf16(float* c, const uint32_t* a, uint32_t b0,
                                         uint32_t b1) {
    asm volatile(
        "mma.sync.aligned.m16n8k16.row.col.f32.bf16.bf16.f32 "
        "{%0,%1,%2,%3},{%4,%5,%6,%7},{%8,%9},{%0,%1,%2,%3};"
        : "+f"(c[0]), "+f"(c[1]), "+f"(c[2]), "+f"(c[3])
        : "r"(a[0]), "r"(a[1]), "r"(a[2]), "r"(a[3]), "r"(b0), "r"(b1));
}
__device__ __forceinline__ void split4(float4 v, uint32_t& h01, uint32_t& h23,
                                       uint32_t& l01, uint32_t& l23) {
    asm("cvt.rn.bf16x2.f32 %0, %1, %2;" : "=r"(h01) : "f"(v.y), "f"(v.x));
    asm("cvt.rn.bf16x2.f32 %0, %1, %2;" : "=r"(h23) : "f"(v.w), "f"(v.z));
    float q0 = v.x - __uint_as_float(h01 << 16);
    float q1 = v.y - __uint_as_float(h01 & 0xffff0000u);
    float q2 = v.z - __uint_as_float(h23 << 16);
    float q3 = v.w - __uint_as_float(h23 & 0xffff0000u);
    asm("cvt.rn.bf16x2.f32 %0, %1, %2;" : "=r"(l01) : "f"(q1), "f"(q0));
    asm("cvt.rn.bf16x2.f32 %0, %1, %2;" : "=r"(l23) : "f"(q3), "f"(q2));
}

// ===========================================================================
// generic fp32 -> bf16 hi/lo split
// ===========================================================================
__global__ __launch_bounds__(256) void cvt_split_p(const float4* __restrict__ src,
                                                   uint2* __restrict__ hp,
                                                   uint2* __restrict__ lp) {
    int i = blockIdx.x * 256 + threadIdx.x;
    float4 v = src[i];
    uint32_t h01, h23, l01, l23;
    split4(v, h01, h23, l01, l23);
    hp[i] = make_uint2(h01, h23);
    lp[i] = make_uint2(l01, l23);
}

// ===========================================================================
// V transpose + split: g_qkv V plane [b][h][k][d] -> g_vt [b][h][d][k] bf16
// ===========================================================================
__global__ __launch_bounds__(256) void vt_split() {
    int idx = blockIdx.x * 256 + threadIdx.x;   // 32*64*512 = 1048576
    int k4 = idx & 511;
    int d = (idx >> 9) & 63;
    int bh = idx >> 15;
    const float* vp = g_qkv + 2 * QKPLANE + ((size_t)bh * SS + k4 * 4) * DD + d;
    float4 v = make_float4(vp[0], vp[64], vp[128], vp[192]);
    uint32_t h01, h23, l01, l23;
    split4(v, h01, h23, l01, l23);
    size_t o = ((size_t)bh * DD + d) * 512 + k4;
    ((uint2*)g_vt_hi)[o] = make_uint2(h01, h23);
    ((uint2*)g_vt_lo)[o] = make_uint2(l01, l23);
}

// ===========================================================================
// softmax over HEAD axis: P[b,h,q,k] = exp(S/32) / sum_h exp(S/32)
// thread handles one (b,q,k4): 16 h-strided float4 loads.
// ===========================================================================
__global__ __launch_bounds__(256) void softmax_h() {
    int idx = blockIdx.x * 256 + threadIdx.x;   // 2*2048*512 = 2097152
    int k4 = idx & 511;
    int q = (idx >> 9) & 2047;
    int b = idx >> 20;
    const size_t hs = (size_t)SS * 512;         // f4 per h-plane
    size_t base = ((size_t)b * HH * SS + q) * 512 + k4;

    const float4* S4 = (const float4*)g_S;
    float4 e[16];
    float4 ds = make_float4(0.f, 0.f, 0.f, 0.f);
#pragma unroll
    for (int h = 0; h < 16; h++) {
        float4 s = S4[base + (size_t)h * hs];
        e[h].x = __expf(s.x * 0.03125f);
        e[h].y = __expf(s.y * 0.03125f);
        e[h].z = __expf(s.z * 0.03125f);
        e[h].w = __expf(s.w * 0.03125f);
        ds.x += e[h].x; ds.y += e[h].y; ds.z += e[h].z; ds.w += e[h].w;
    }
    float4 r;
    r.x = __fdividef(1.f, ds.x);
    r.y = __fdividef(1.f, ds.y);
    r.z = __fdividef(1.f, ds.z);
    r.w = __fdividef(1.f, ds.w);
    uint2* phi = (uint2*)g_p_hi;
    uint2* plo = (uint2*)g_p_lo;
#pragma unroll
    for (int h = 0; h < 16; h++) {
        float4 p = make_float4(e[h].x * r.x, e[h].y * r.y, e[h].z * r.z, e[h].w * r.w);
        uint32_t h01, h23, l01, l23;
        split4(p, h01, h23, l01, l23);
        size_t o = base + (size_t)h * hs;
        phi[o] = make_uint2(h01, h23);
        plo[o] = make_uint2(l01, l23);
    }
}

// ===========================================================================
// Unified HMMA bf16-split NT GEMM: C[M x NT-tiles] = A[M,K] @ W[N,K]^T
// MODE 0: out-proj (bias, row-major out N=1024)
// MODE 1: QKV (bias, scatter into g_qkv)
// MODE 2: scores (z=(b,h), out fp32 g_S row-stride 2048)
// MODE 3: ctx (z=(b,h), NT=64, out scatter into g_ctx)
// ===========================================================================
template <int MODE, int NT, int K>
__global__ __launch_bounds__(256, 2) void tgemm(
    const __nv_bfloat16* __restrict__ Ah0, const __nv_bfloat16* __restrict__ Al0,
    const __nv_bfloat16* __restrict__ Wh0, const __nv_bfloat16* __restrict__ Wl0,
    const float* __restrict__ bias, float* __restrict__ Cout,
    int strideA, int strideW) {
    extern __shared__ char dsm[];
    uint32_t sbase = smem_u32(dsm);
    constexpr int TILE_A = 10240;          // 128 rows * 80B
    constexpr int TILE_W = NT * 80;
    constexpr int BUF = 2 * TILE_A + 2 * TILE_W;
    constexpr int NP = NT / 32;

    int z = blockIdx.z;
    const __nv_bfloat16* Ah = Ah0 + (size_t)z * strideA;
    const __nv_bfloat16* Al = Al0 + (size_t)z * strideA;
    const __nv_bfloat16* Wh = Wh0 + (size_t)z * strideW;
    const __nv_bfloat16* Wl = Wl0 + (size_t)z * strideW;

    int tid = threadIdx.x, lane = tid & 31, wid = tid >> 5;
    int wm = wid & 3, wn = wid >> 2;
    int m0 = blockIdx.y * 128, n0 = blockIdx.x * NT;

    float acc[2][2 * NP][4];
#pragma unroll
    for (int i = 0; i < 2; i++)
#pragma unroll
        for (int j = 0; j < 2 * NP; j++)
#pragma unroll
            for (int q = 0; q < 4; q++) acc[i][j][q] = 0.f;

    const int NC = K / 32;
    const int lrow = tid >> 2;
    const int seg = tid & 3;

    auto issue = [&](int c) {
        uint32_t sb = sbase + (c & 1) * BUF;
        int gcol = c * 32 + seg * 8;
#pragma unroll
        for (int rr = 0; rr < 2; rr++) {
            int row = lrow + rr * 64;
            uint32_t soff = (uint32_t)(row * 80 + seg * 16);
            cp_async16(sb + soff, Ah + (size_t)(m0 + row) * K + gcol);
            cp_async16(sb + TILE_A + soff, Al + (size_t)(m0 + row) * K + gcol);
        }
#pragma unroll
        for (int rr = 0; rr < NT / 64; rr++) {
            int row = lrow + rr * 64;
            uint32_t soff = (uint32_t)(row * 80 + seg * 16);
            cp_async16(sb + 2 * TILE_A + soff, Wh + (size_t)(n0 + row) * K + gcol);
            cp_async16(sb + 2 * TILE_A + TILE_W + soff, Wl + (size_t)(n0 + row) * K + gcol);
        }
        cp_commit();
    };

    issue(0);

    for (int c = 0; c < NC; c++) {
        if (c + 1 < NC) {
            issue(c + 1);
            asm volatile("cp.async.wait_group 1;\n" ::: "memory");
        } else {
            asm volatile("cp.async.wait_group 0;\n" ::: "memory");
        }
        __syncthreads();

        uint32_t sb = sbase + (c & 1) * BUF;
        uint32_t a_addr = sb + (uint32_t)((wm * 32 + (lane & 15)) * 80 + (lane >> 4) * 16);
        uint32_t b_addr = sb + 2 * TILE_A +
                          (uint32_t)((wn * (NT / 2) + (lane >> 4) * 8 + (lane & 7)) * 80 +
                                     ((lane >> 3) & 1) * 16);

#pragma unroll
        for (int ks = 0; ks < 2; ks++) {
            uint32_t ah[2][4], al[2][4];
#pragma unroll
            for (int mb = 0; mb < 2; mb++) {
                uint32_t ao = a_addr + ks * 32 + mb * (16 * 80);
                ldsm4(ah[mb][0], ah[mb][1], ah[mb][2], ah[mb][3], ao);
                ldsm4(al[mb][0], al[mb][1], al[mb][2], al[mb][3], ao + TILE_A);
            }
#pragma unroll
            for (int np = 0; np < NP; np++) {
                uint32_t bo = b_addr + ks * 32 + np * (16 * 80);
                uint32_t h0, h1, h2, h3, l0, l1, l2, l3;
                ldsm4(h0, h1, h2, h3, bo);
                ldsm4(l0, l1, l2, l3, bo + TILE_W);
#pragma unroll
                for (int mb = 0; mb < 2; mb++) {
                    mma_bf16(acc[mb][2 * np],     ah[mb], h0, h1);
                    mma_bf16(acc[mb][2 * np],     al[mb], h0, h1);
                    mma_bf16(acc[mb][2 * np],     ah[mb], l0, l1);
                    mma_bf16(acc[mb][2 * np + 1], ah[mb], h2, h3);
                    mma_bf16(acc[mb][2 * np + 1], al[mb], h2, h3);
                    mma_bf16(acc[mb][2 * np + 1], ah[mb], l2, l3);
                }
            }
        }
        __syncthreads();
    }

    int lr = lane >> 2, lc = lane & 3;
#pragma unroll
    for (int mb = 0; mb < 2; mb++) {
#pragma unroll
        for (int nb = 0; nb < 2 * NP; nb++) {
            int n = n0 + wn * (NT / 2) + nb * 8 + lc * 2;
            int m_lo = m0 + wm * 32 + mb * 16 + lr;
            float* a4 = acc[mb][nb];
            if constexpr (MODE == 0) {
                float2 bv = *(const float2*)(bias + n);
                *(float2*)(Cout + (size_t)m_lo * 1024 + n) =
                    make_float2(a4[0] + bv.x, a4[1] + bv.y);
                *(float2*)(Cout + (size_t)(m_lo + 8) * 1024 + n) =
                    make_float2(a4[2] + bv.x, a4[3] + bv.y);
            } else if constexpr (MODE == 1) {
                float2 bv = *(const float2*)(bias + n);
                int which = n >> 10;
                int h = (n & 1023) >> 6;
                int d = n & 63;
#pragma unroll
                for (int half = 0; half < 2; half++) {
                    int m = m_lo + half * 8;
                    int b = m >> 11;
                    int s = m & 2047;
                    float* dst = g_qkv +
                        ((((size_t)which * BB + b) * HH + h) * SS + s) * DD + d;
                    *(float2*)dst = make_float2(a4[2 * half] + bv.x,
                                                a4[2 * half + 1] + bv.y);
                }
            } else if constexpr (MODE == 2) {
                float* Sp = Cout + (size_t)z * SPLANE;
                *(float2*)(Sp + (size_t)m_lo * SS + n) = make_float2(a4[0], a4[1]);
                *(float2*)(Sp + (size_t)(m_lo + 8) * SS + n) = make_float2(a4[2], a4[3]);
            } else {
                int b = z >> 4, h = z & 15;
                float* base = g_ctx + (size_t)(b * SS + m_lo) * EE + h * DD + n;
                *(float2*)base = make_float2(a4[0], a4[1]);
                *(float2*)(base + 8 * EE) = make_float2(a4[2], a4[3]);
            }
        }
    }
}

// ===========================================================================
extern "C" void kernel_launch(void* const* d_in, const int* in_sizes, int n_in,
                              void* d_out, int out_size) {
    const float* x     = (const float*)d_in[0];
    const float* w_qkv = (const float*)d_in[1];
    const float* b_qkv = (const float*)d_in[2];
    const float* w_out = (const float*)d_in[3];
    const float* b_out = (const float*)d_in[4];
    float* out = (float*)d_out;

    // symbol addresses
    void *p_qkv, *p_ctx, *p_S, *p_phi, *p_plo, *p_ahi, *p_alo, *p_wqh, *p_wql,
         *p_woh, *p_wol, *p_qhi, *p_qlo, *p_khi, *p_klo, *p_vth, *p_vtl;
    cudaGetSymbolAddress(&p_qkv, g_qkv);
    cudaGetSymbolAddress(&p_ctx, g_ctx);
    cudaGetSymbolAddress(&p_S, g_S);
    cudaGetSymbolAddress(&p_phi, g_p_hi);
    cudaGetSymbolAddress(&p_plo, g_p_lo);
    cudaGetSymbolAddress(&p_ahi, g_a_hi);
    cudaGetSymbolAddress(&p_alo, g_a_lo);
    cudaGetSymbolAddress(&p_wqh, g_wq_hi);
    cudaGetSymbolAddress(&p_wql, g_wq_lo);
    cudaGetSymbolAddress(&p_woh, g_wo_hi);
    cudaGetSymbolAddress(&p_wol, g_wo_lo);
    cudaGetSymbolAddress(&p_qhi, g_q_hi);
    cudaGetSymbolAddress(&p_qlo, g_q_lo);
    cudaGetSymbolAddress(&p_khi, g_k_hi);
    cudaGetSymbolAddress(&p_klo, g_k_lo);
    cudaGetSymbolAddress(&p_vth, g_vt_hi);
    cudaGetSymbolAddress(&p_vtl, g_vt_lo);

    const int SM128 = 2 * (2 * 10240 + 2 * 10240);   // 81920
    const int SM64  = 2 * (2 * 10240 + 2 * 5120);    // 61440
    cudaFuncSetAttribute(tgemm<1, 128, 1024>, cudaFuncAttributeMaxDynamicSharedMemorySize, SM128);
    cudaFuncSetAttribute(tgemm<0, 128, 1024>, cudaFuncAttributeMaxDynamicSharedMemorySize, SM128);
    cudaFuncSetAttribute(tgemm<2, 128, 64>,   cudaFuncAttributeMaxDynamicSharedMemorySize, SM128);
    cudaFuncSetAttribute(tgemm<3, 64, 2048>,  cudaFuncAttributeMaxDynamicSharedMemorySize, SM64);

    // 1) split x, w_qkv, w_out
    cvt_split_p<<<4096, 256>>>((const float4*)x, (uint2*)p_ahi, (uint2*)p_alo);
    cvt_split_p<<<3072, 256>>>((const float4*)w_qkv, (uint2*)p_wqh, (uint2*)p_wql);
    cvt_split_p<<<1024, 256>>>((const float4*)w_out, (uint2*)p_woh, (uint2*)p_wol);

    // 2) QKV projection -> g_qkv
    tgemm<1, 128, 1024><<<dim3(24, 32, 1), 256, SM128>>>(
        (const __nv_bfloat16*)p_ahi, (const __nv_bfloat16*)p_alo,
        (const __nv_bfloat16*)p_wqh, (const __nv_bfloat16*)p_wql,
        b_qkv, nullptr, 0, 0);

    // 3) split Q, K planes; transpose+split V
    cvt_split_p<<<4096, 256>>>((const float4*)p_qkv, (uint2*)p_qhi, (uint2*)p_qlo);
    cvt_split_p<<<4096, 256>>>((const float4*)((const float*)p_qkv + QKPLANE),
                               (uint2*)p_khi, (uint2*)p_klo);
    vt_split<<<4096, 256>>>();

    // 4) scores S = Q K^T (batched over 32 (b,h))
    tgemm<2, 128, 64><<<dim3(16, 16, 32), 256, SM128>>>(
        (const __nv_bfloat16*)p_qhi, (const __nv_bfloat16*)p_qlo,
        (const __nv_bfloat16*)p_khi, (const __nv_bfloat16*)p_klo,
        nullptr, (float*)p_S, SS * DD, SS * DD);

    // 5) softmax over heads -> P hi/lo
    softmax_h<<<8192, 256>>>();

    // 6) ctx = P V (batched over 32 (b,h))
    tgemm<3, 64, 2048><<<dim3(1, 16, 32), 256, SM64>>>(
        (const __nv_bfloat16*)p_phi, (const __nv_bfloat16*)p_plo,
        (const __nv_bfloat16*)p_vth, (const __nv_bfloat16*)p_vtl,
        nullptr, nullptr, (int)SPLANE, DD * SS);

    // 7) split ctx, out-projection
    cvt_split_p<<<4096, 256>>>((const float4*)p_ctx, (uint2*)p_ahi, (uint2*)p_alo);
    tgemm<0, 128, 1024><<<dim3(8, 32, 1), 256, SM128>>>(
        (const __nv_bfloat16*)p_ahi, (const __nv_bfloat16*)p_alo,
        (const __nv_bfloat16*)p_woh, (const __nv_bfloat16*)p_wol,
        b_out, out, 0, 0);
}